// round 7
// baseline (speedup 1.0000x reference)
#include <cuda_runtime.h>

#define R_   64
#define I_   256
#define O_   256
#define MT   128          // entities per tile
#define TPB  512
#define GRID 152

// W_sum[r, o] = sum_i W[r, i, o]  (64 x 256 fp32)
__device__ __align__(16) float g_wsum[R_ * O_];

__global__ void wsum_kernel(const float* __restrict__ W) {
    int r = blockIdx.x;
    int o = threadIdx.x;
    const float* p = W + (size_t)r * I_ * O_ + o;
    float s = 0.f;
#pragma unroll 8
    for (int i = 0; i < I_; ++i) s += p[(size_t)i * O_];
    g_wsum[r * O_ + o] = s;
}

__device__ __forceinline__ unsigned long long dup2(float f) {
    unsigned long long d;
    asm("mov.b64 %0, {%1, %1};" : "=l"(d) : "f"(f));
    return d;
}
__device__ __forceinline__ void fma2(unsigned long long& d,
                                     unsigned long long a,
                                     unsigned long long b) {
    asm("fma.rn.f32x2 %0, %1, %2, %0;" : "+l"(d) : "l"(a), "l"(b));
}
__device__ __forceinline__ float2 unpk(unsigned long long v) {
    float lo, hi;
    asm("mov.b64 {%0, %1}, %2;" : "=f"(lo), "=f"(hi) : "l"(v));
    return make_float2(lo, hi);
}

// Dynamic shared layout:
//   [0,      65536)  : s_b  u64[64][128]    W_sum as column-pairs (chunk-invariant)
//   [65536, 131072)  : s_a  f32[2][64][128] xsum/cs, k-major, double-buffered
#define SMEM_BYTES 131072

__global__ __launch_bounds__(TPB, 1) void rgcn_kernel(
    const float* __restrict__ x, const float* __restrict__ cs,
    float* __restrict__ out, int E)
{
    extern __shared__ __align__(16) char smem[];
    unsigned long long* s_b = (unsigned long long*)smem;
    float*              s_a = (float*)(smem + 65536);

    const int tid = threadIdx.x;
    const int tx  = tid & 31;     // column-pair base (stride 32)
    const int ty  = tid >> 5;     // warp id = entity group (8 entities each)

    // ---- load W_sum into shared once ----
    {
        const float4* src = (const float4*)g_wsum;   // 4096 x 16B
        float4*       dst = (float4*)s_b;
        for (int i = tid; i < 4096; i += TPB) dst[i] = src[i];
    }

    const int nch = (E + MT - 1) / MT;

    // ---- stage one chunk: sa[k][el] = xsum(e) / cs[e,k] ----
    // 4 threads per entity: q = tid&3 owns a quarter of the x row and cs row.
    auto stage = [&](int chunk, int buf) {
        int  el = tid >> 2;                 // entity-in-tile 0..127
        int  q  = tid & 3;                  // quarter
        long e  = (long)chunk * MT + el;
        bool valid = (e < E);
        float* sa = s_a + buf * 8192;
        float4 c[4];
        float  xs = 0.f;
        if (valid) {
            // cs quarter: 16 floats
            const float4* cp = (const float4*)(cs + e * (long)R_ + q * 16);
#pragma unroll
            for (int i = 0; i < 4; ++i) c[i] = cp[i];
            // x quarter: 64 floats
            const float4* xp = (const float4*)(x + e * (long)I_ + q * 64);
#pragma unroll
            for (int i = 0; i < 16; ++i) {
                float4 v = xp[i];
                xs += (v.x + v.y) + (v.z + v.w);
            }
        }
        // combine 4 quarter-sums — executed by ALL lanes (full-mask shfl must
        // not sit under the e<E divergence; xs==0 on invalid lanes is unused).
        xs += __shfl_xor_sync(0xffffffffu, xs, 1);
        xs += __shfl_xor_sync(0xffffffffu, xs, 2);
        if (valid) {
            // write 16 k-rows: sa[k][el] = xs / cs
#pragma unroll
            for (int i = 0; i < 4; ++i) {
                int kb = q * 16 + 4 * i;
                sa[(kb + 0) * 128 + el] = __fdividef(xs, c[i].x);
                sa[(kb + 1) * 128 + el] = __fdividef(xs, c[i].y);
                sa[(kb + 2) * 128 + el] = __fdividef(xs, c[i].z);
                sa[(kb + 3) * 128 + el] = __fdividef(xs, c[i].w);
            }
        } else {
#pragma unroll
            for (int i = 0; i < 16; ++i) sa[(q * 16 + i) * 128 + el] = 0.f;
        }
    };

    int c0 = blockIdx.x;
    if (c0 < nch) stage(c0, 0);
    __syncthreads();

    int buf = 0;
    for (int chunk = c0; chunk < nch; chunk += GRID) {
        int nxt = chunk + GRID;
        if (nxt < nch) stage(nxt, buf ^ 1);   // overlap next-chunk LDG with GEMM

        // ---- GEMM: acc[i][j] = sum_k sa[k][e_i] * wsum[k][colpair tx+32j] ----
        unsigned long long acc[8][4];
#pragma unroll
        for (int i = 0; i < 8; ++i)
#pragma unroll
            for (int j = 0; j < 4; ++j) acc[i][j] = 0ull;

        const float* sa = s_a + buf * 8192;
#pragma unroll 8
        for (int k = 0; k < 64; ++k) {
            // B-frag: 4 col-pairs, stride 32 (256B contiguous per warp)
            const unsigned long long* sb = s_b + k * 128 + tx;
            unsigned long long bv0 = sb[0];
            unsigned long long bv1 = sb[32];
            unsigned long long bv2 = sb[64];
            unsigned long long bv3 = sb[96];
            // A-frag: 8 entities, single-address broadcast per warp
            float4 a0 = *(const float4*)(sa + k * 128 + ty * 8);
            float4 a1 = *(const float4*)(sa + k * 128 + ty * 8 + 4);
            float av[8] = {a0.x, a0.y, a0.z, a0.w, a1.x, a1.y, a1.z, a1.w};
#pragma unroll
            for (int i = 0; i < 8; ++i) {
                unsigned long long ad = dup2(av[i]);
                fma2(acc[i][0], ad, bv0);
                fma2(acc[i][1], ad, bv1);
                fma2(acc[i][2], ad, bv2);
                fma2(acc[i][3], ad, bv3);
            }
        }

        // ---- epilogue: pure coalesced store (xsum already folded in) ----
        long eb = (long)chunk * MT;
#pragma unroll
        for (int i = 0; i < 8; ++i) {
            long e = eb + ty * 8 + i;
            if (e < E) {
                float2* op = (float2*)(out + e * (long)O_);
#pragma unroll
                for (int j = 0; j < 4; ++j)
                    op[tx + 32 * j] = unpk(acc[i][j]);
            }
        }

        __syncthreads();
        buf ^= 1;
    }
}

extern "C" void kernel_launch(void* const* d_in, const int* in_sizes, int n_in,
                              void* d_out, int out_size) {
    const float* x  = (const float*)d_in[0];
    const float* cs = (const float*)d_in[1];
    const float* W  = (const float*)d_in[2];
    // d_in[3] = edge_index : dead in the reference computation, never read.
    float* out = (float*)d_out;

    int E = in_sizes[1] / R_;   // cs is (E, 64)

    cudaFuncSetAttribute(rgcn_kernel,
                         cudaFuncAttributeMaxDynamicSharedMemorySize, SMEM_BYTES);

    wsum_kernel<<<R_, O_>>>(W);
    rgcn_kernel<<<GRID, TPB, SMEM_BYTES>>>(x, cs, out, E);
}

// round 10
// speedup vs baseline: 1.0333x; 1.0333x over previous
#include <cuda_runtime.h>

#define R_   64
#define I_   256
#define O_   256
#define MT   128          // entities per tile
#define TPB  512
#define GRID 152

// W_sum[r, o] = sum_i W[r, i, o]  (64 x 256 fp32)
__device__ __align__(16) float g_wsum[R_ * O_];
// x row sums, computed by a dedicated streaming kernel
__device__ float g_xsum[1 << 20];

__global__ void wsum_kernel(const float* __restrict__ W) {
    int r = blockIdx.x;
    int o = threadIdx.x;
    const float* p = W + (size_t)r * I_ * O_ + o;
    float s = 0.f;
#pragma unroll 8
    for (int i = 0; i < I_; ++i) s += p[(size_t)i * O_];
    g_wsum[r * O_ + o] = s;
}

// warp-per-row streaming reduction of x (102 MB read, pure BW)
__global__ void xsum_kernel(const float* __restrict__ x, int E) {
    int w    = (blockIdx.x * blockDim.x + threadIdx.x) >> 5;
    int lane = threadIdx.x & 31;
    int nw   = (gridDim.x * blockDim.x) >> 5;
    for (long e = w; e < E; e += nw) {
        const float4* p = (const float4*)(x + e * (long)I_);
        float4 a = p[lane];
        float4 b = p[lane + 32];
        float s = (a.x + a.y) + (a.z + a.w) + (b.x + b.y) + (b.z + b.w);
#pragma unroll
        for (int off = 16; off; off >>= 1)
            s += __shfl_xor_sync(0xffffffffu, s, off);
        if (lane == 0) g_xsum[e] = s;
    }
}

__device__ __forceinline__ unsigned long long dup2(float f) {
    unsigned long long d;
    asm("mov.b64 %0, {%1, %1};" : "=l"(d) : "f"(f));
    return d;
}
__device__ __forceinline__ void fma2(unsigned long long& d,
                                     unsigned long long a,
                                     unsigned long long b) {
    asm("fma.rn.f32x2 %0, %1, %2, %0;" : "+l"(d) : "l"(a), "l"(b));
}
__device__ __forceinline__ float2 unpk(unsigned long long v) {
    float lo, hi;
    asm("mov.b64 {%0, %1}, %2;" : "=f"(lo), "=f"(hi) : "l"(v));
    return make_float2(lo, hi);
}

// Dynamic shared layout:
//   [0,      65536)  : s_b  u64[64][128]    W_sum as column-pairs (chunk-invariant)
//   [65536, 131072)  : s_a  f32[2][64][128] xsum/cs, k-major, double-buffered
#define SMEM_BYTES 131072

__global__ __launch_bounds__(TPB, 1) void rgcn_kernel(
    const float* __restrict__ cs, float* __restrict__ out, int E)
{
    extern __shared__ __align__(16) char smem[];
    unsigned long long* s_b = (unsigned long long*)smem;
    float*              s_a = (float*)(smem + 65536);

    const int tid = threadIdx.x;
    const int tx  = tid & 31;     // column-pair base (stride 32)
    const int ty  = tid >> 5;     // warp id = entity group (8 entities each)

    // ---- load W_sum into shared once ----
    {
        const float4* src = (const float4*)g_wsum;   // 4096 x 16B
        float4*       dst = (float4*)s_b;
        for (int i = tid; i < 4096; i += TPB) dst[i] = src[i];
    }

    const int nch = (E + MT - 1) / MT;

    // ---- stage one chunk (LIGHT: cs + xsum only, ~32.5 KB per chunk) ----
    // 4 threads per entity: q = tid&3 owns a 16-value quarter of the cs row.
    auto stage = [&](int chunk, int buf) {
        int  el = tid >> 2;                 // entity-in-tile 0..127
        int  q  = tid & 3;                  // quarter
        long e  = (long)chunk * MT + el;
        float* sa = s_a + buf * 8192;
        if (e < E) {
            float xs = g_xsum[e];           // 4 lanes same addr: L1 broadcast
            float4 c[4];
            const float4* cp = (const float4*)(cs + e * (long)R_ + q * 16);
#pragma unroll
            for (int i = 0; i < 4; ++i) c[i] = cp[i];
#pragma unroll
            for (int i = 0; i < 4; ++i) {
                int kb = q * 16 + 4 * i;
                sa[(kb + 0) * 128 + el] = __fdividef(xs, c[i].x);
                sa[(kb + 1) * 128 + el] = __fdividef(xs, c[i].y);
                sa[(kb + 2) * 128 + el] = __fdividef(xs, c[i].z);
                sa[(kb + 3) * 128 + el] = __fdividef(xs, c[i].w);
            }
        } else {
#pragma unroll
            for (int i = 0; i < 16; ++i) sa[(q * 16 + i) * 128 + el] = 0.f;
        }
    };

    int c0 = blockIdx.x;
    if (c0 < nch) stage(c0, 0);
    __syncthreads();

    int buf = 0;
    for (int chunk = c0; chunk < nch; chunk += GRID) {
        int nxt = chunk + GRID;
        if (nxt < nch) stage(nxt, buf ^ 1);   // cheap; hides under GEMM

        // ---- GEMM: acc[i][j] = sum_k sa[k][e_i] * wsum[k][colpair tx+32j] ----
        unsigned long long acc[8][4];
#pragma unroll
        for (int i = 0; i < 8; ++i)
#pragma unroll
            for (int j = 0; j < 4; ++j) acc[i][j] = 0ull;

        const float* sa = s_a + buf * 8192;

        // software-pipelined k-loop: fragments for k+1 loaded during k's FMAs
        unsigned long long cb0, cb1, cb2, cb3, nb0, nb1, nb2, nb3;
        float4 ca0, ca1, na0, na1;
        {
            const unsigned long long* sb = s_b + tx;
            cb0 = sb[0]; cb1 = sb[32]; cb2 = sb[64]; cb3 = sb[96];
            ca0 = *(const float4*)(sa + ty * 8);
            ca1 = *(const float4*)(sa + ty * 8 + 4);
        }
#pragma unroll 8
        for (int k = 0; k < 64; ++k) {
            if (k < 63) {
                const unsigned long long* sb = s_b + (k + 1) * 128 + tx;
                nb0 = sb[0]; nb1 = sb[32]; nb2 = sb[64]; nb3 = sb[96];
                na0 = *(const float4*)(sa + (k + 1) * 128 + ty * 8);
                na1 = *(const float4*)(sa + (k + 1) * 128 + ty * 8 + 4);
            }
            float av[8] = {ca0.x, ca0.y, ca0.z, ca0.w,
                           ca1.x, ca1.y, ca1.z, ca1.w};
#pragma unroll
            for (int i = 0; i < 8; ++i) {
                unsigned long long ad = dup2(av[i]);
                fma2(acc[i][0], ad, cb0);
                fma2(acc[i][1], ad, cb1);
                fma2(acc[i][2], ad, cb2);
                fma2(acc[i][3], ad, cb3);
            }
            cb0 = nb0; cb1 = nb1; cb2 = nb2; cb3 = nb3;
            ca0 = na0; ca1 = na1;
        }

        // ---- epilogue: pure coalesced store (xsum folded at stage) ----
        long eb = (long)chunk * MT;
#pragma unroll
        for (int i = 0; i < 8; ++i) {
            long e = eb + ty * 8 + i;
            if (e < E) {
                float2* op = (float2*)(out + e * (long)O_);
#pragma unroll
                for (int j = 0; j < 4; ++j)
                    op[tx + 32 * j] = unpk(acc[i][j]);
            }
        }

        __syncthreads();
        buf ^= 1;
    }
}

extern "C" void kernel_launch(void* const* d_in, const int* in_sizes, int n_in,
                              void* d_out, int out_size) {
    const float* x  = (const float*)d_in[0];
    const float* cs = (const float*)d_in[1];
    const float* W  = (const float*)d_in[2];
    // d_in[3] = edge_index : dead in the reference computation, never read.
    float* out = (float*)d_out;

    int E = in_sizes[1] / R_;   // cs is (E, 64)

    cudaFuncSetAttribute(rgcn_kernel,
                         cudaFuncAttributeMaxDynamicSharedMemorySize, SMEM_BYTES);

    wsum_kernel<<<R_, O_>>>(W);
    xsum_kernel<<<1024, 256>>>(x, E);
    rgcn_kernel<<<GRID, TPB, SMEM_BYTES>>>(cs, out, E);
}